// round 3
// baseline (speedup 1.0000x reference)
#include <cuda_runtime.h>
#include <math.h>

#define BB 16
#define AA 3
#define CC 80
#define HH 76
#define WW 76
#define TT 50
#define PLANE (HH*WW)            // 5776
#define NPLANES (BB*AA)          // 48 conf planes
#define NT (BB*TT)               // 800 targets
#define CONF_BLOCKS NPLANES      // 48
#define TGT_BLOCKS 100           // 8 warps each -> exactly 800 warps
#define GRID (CONF_BLOCKS + TGT_BLOCKS)   // 148 = #SMs
#define NBITWORDS ((NPLANES*PLANE + 31)/32)   // 8664 words = 34.7KB

__constant__ float c_anch[18] = {10.f,13.f,16.f,30.f,33.f,23.f,30.f,61.f,62.f,45.f,
                                 59.f,119.f,116.f,90.f,156.f,198.f,373.f,326.f};

__device__ float g_part[NPLANES];   // per-plane conf sums
__device__ float g_tl[NT];          // per-target xywh loss (already *scale)
__device__ float g_tc[NT];          // per-target cls loss
__device__ int   g_cell[NT];        // flat cell id, -1 if unassigned
__device__ int   g_valid[NT];       // 0/1
__device__ int   g_done = 0;        // completion counter (reset by last block)

__device__ __forceinline__ float sigf(float z) { return 1.f / (1.f + expf(-z)); }

__global__ void __launch_bounds__(256, 1) fused_kernel(const float* __restrict__ in,
                                                       const float* __restrict__ tgt,
                                                       float* __restrict__ out) {
    __shared__ unsigned bm[NBITWORDS];   // bitmap for last-block dedupe (34.7KB)
    __shared__ float sm_red[8];
    __shared__ int  s_islast;

    int tid = threadIdx.x;

    // ───────────── phase A ─────────────
    if (blockIdx.x < CONF_BLOCKS) {
        // conf-plane sigmoid reduction (float4 vectorized)
        int plane = blockIdx.x;
        int b = plane / AA, a = plane - b * AA;
        const float4* p = (const float4*)(in + (size_t)(b * 255 + a * 85 + 4) * PLANE);
        float s = 0.f;
        for (int i = tid; i < PLANE / 4; i += blockDim.x) {
            float4 v = p[i];
            s += sigf(v.x) + sigf(v.y) + sigf(v.z) + sigf(v.w);
        }
        for (int o = 16; o > 0; o >>= 1) s += __shfl_down_sync(0xffffffffu, s, o);
        int w = tid >> 5, l = tid & 31;
        if (l == 0) sm_red[w] = s;
        __syncthreads();
        if (w == 0) {
            s = (l < 8) ? sm_red[l] : 0.f;
            for (int o = 4; o > 0; o >>= 1) s += __shfl_down_sync(0xffffffffu, s, o);
            if (l == 0) g_part[plane] = s;
        }
    } else {
        // target phase: one warp per target
        int w = tid >> 5, l = tid & 31;
        int t = (blockIdx.x - CONF_BLOCKS) * 8 + w;   // 0..799, always in range

        int b = t / TT;
        const float* t5 = tgt + b * (TT * 5) + (t - b * TT) * 5;
        float tc = t5[0], tx = t5[1], ty = t5[2], tw = t5[3], th = t5[4];
        int valid = ((tc + tx + ty + tw + th) != 0.f);

        // best of 9 anchors (shared-center IoU), first-max argmax
        float best = -1e30f; int bi = 0;
        #pragma unroll
        for (int k = 0; k < 9; k++) {
            float aw = c_anch[2 * k]     * (1.f / 608.f);
            float ah = c_anch[2 * k + 1] * (1.f / 608.f);
            float inter = fminf(tw, aw) * fminf(th, ah);
            float uni   = tw * th + aw * ah - inter;
            float iou   = inter / uni;
            if (iou > best) { best = iou; bi = k; }
        }
        int assigned = valid && (bi < AA);

        float acc_xy = 0.f, acc_cls = 0.f;
        int mycell = -1;

        if (assigned) {
            int a_n = bi;
            int gi = (int)(tx * (float)WW); gi = min(max(gi, 0), WW - 1);
            int gj = (int)(ty * (float)HH); gj = min(max(gj, 0), HH - 1);
            int pos = gj * WW + gi;
            mycell = ((b * AA + a_n) * HH + gj) * WW + gi;

            float aw_s = c_anch[2 * a_n], ah_s = c_anch[2 * a_n + 1];
            float tx_t = tx * (float)WW - (float)gi;
            float ty_t = ty * (float)HH - (float)gj;
            float tw_t = logf(tw * 608.f / aw_s);
            float th_t = logf(th * 608.f / ah_s);
            float scale = 2.f * ty * tw;      // faithful to reference quirk
            int ci = (int)tc;

            const float* cp = in + (size_t)(b * 255 + a_n * 85) * PLANE + pos;

            // lanes split the 85 channels (skip conf ch 4)
            #pragma unroll
            for (int r = 0; r < 3; r++) {
                int ch = l + 32 * r;
                if (ch < 85 && ch != 4) {
                    float v = cp[(size_t)ch * PLANE];
                    if (ch == 0)      acc_xy += scale * fabsf(sigf(v) - tx_t);
                    else if (ch == 1) acc_xy += scale * fabsf(sigf(v) - ty_t);
                    else if (ch == 2) acc_xy += scale * fabsf(v - tw_t);
                    else if (ch == 3) acc_xy += scale * fabsf(v - th_t);
                    else {
                        int c = ch - 5;
                        float p = sigf(v);
                        acc_cls += (c == ci) ? -logf(p) : -log1pf(-p);
                    }
                }
            }
            for (int o = 16; o > 0; o >>= 1) {
                acc_xy  += __shfl_down_sync(0xffffffffu, acc_xy, o);
                acc_cls += __shfl_down_sync(0xffffffffu, acc_cls, o);
            }
        }
        if (l == 0) {
            g_tl[t] = acc_xy;
            g_tc[t] = acc_cls;
            g_cell[t] = mycell;
            g_valid[t] = valid;
        }
    }

    // ───────────── completion protocol ─────────────
    __syncthreads();
    __threadfence();
    if (tid == 0) {
        int old = atomicAdd(&g_done, 1);
        s_islast = (old == GRID - 1);
    }
    __syncthreads();
    if (!s_islast) return;

    // ───────────── phase B: last block does dedupe + final sums ─────────────
    __shared__ float s_lxywh, s_lcls, s_conf;
    __shared__ int s_valid, s_unique;
    if (tid == 0) { s_lxywh = 0.f; s_lcls = 0.f; s_conf = 0.f; s_valid = 0; s_unique = 0; }
    for (int i = tid; i < NBITWORDS; i += blockDim.x) bm[i] = 0u;
    __syncthreads();

    float lx = 0.f, lc = 0.f, cf = 0.f;
    int va = 0, un = 0;
    for (int t = tid; t < NT; t += blockDim.x) {
        lx += g_tl[t];
        lc += g_tc[t];
        va += g_valid[t];
        int cell = g_cell[t];
        if (cell >= 0) {
            unsigned mask = 1u << (cell & 31);
            unsigned old = atomicOr(&bm[cell >> 5], mask);
            if (!(old & mask)) un++;
        }
    }
    if (tid < NPLANES) cf = g_part[tid];

    for (int o = 16; o > 0; o >>= 1) {
        lx += __shfl_down_sync(0xffffffffu, lx, o);
        lc += __shfl_down_sync(0xffffffffu, lc, o);
        cf += __shfl_down_sync(0xffffffffu, cf, o);
        va += __shfl_down_sync(0xffffffffu, va, o);
        un += __shfl_down_sync(0xffffffffu, un, o);
    }
    if ((tid & 31) == 0) {
        atomicAdd(&s_lxywh, lx);
        atomicAdd(&s_lcls, lc);
        atomicAdd(&s_conf, cf);
        atomicAdd(&s_valid, va);
        atomicAdd(&s_unique, un);
    }
    __syncthreads();

    if (tid == 0) {
        float nt = fmaxf((float)s_valid, 1.f);
        out[0] = s_conf - (float)s_unique + s_lxywh / nt + s_lcls;
        g_done = 0;   // reset for next graph replay
    }
}

extern "C" void kernel_launch(void* const* d_in, const int* in_sizes, int n_in,
                              void* d_out, int out_size) {
    const float* in  = (const float*)d_in[0];   // [16, 255, 76, 76]
    const float* tgt = (const float*)d_in[1];   // [16, 250]
    float* out = (float*)d_out;
    fused_kernel<<<GRID, 256>>>(in, tgt, out);
}

// round 4
// speedup vs baseline: 1.5312x; 1.5312x over previous
#include <cuda_runtime.h>
#include <math.h>

#define BB 16
#define AA 3
#define CC 80
#define HH 76
#define WW 76
#define TT 50
#define PLANE (HH*WW)            // 5776
#define NPLANES (BB*AA)          // 48 conf planes
#define NT (BB*TT)               // 800 targets
#define CONF_BLOCKS NPLANES      // 48
#define TGT_BLOCKS 50            // 16 warps each -> exactly 800 warps
#define DEDUPE_BLOCK (CONF_BLOCKS + TGT_BLOCKS)      // 98
#define GRID (CONF_BLOCKS + TGT_BLOCKS + 1)          // 99 blocks, one wave
#define NTHREADS 512
#define NBITWORDS ((NPLANES*PLANE + 31)/32)          // 8664 words = 34.7KB

__constant__ float c_anch[18] = {10.f,13.f,16.f,30.f,33.f,23.f,30.f,61.f,62.f,45.f,
                                 59.f,119.f,116.f,90.f,156.f,198.f,373.f,326.f};

__device__ float g_confp[CONF_BLOCKS];  // per-conf-block partial
__device__ float g_lxp[TGT_BLOCKS];     // per-target-block xywh partial
__device__ float g_lcp[TGT_BLOCKS];     // per-target-block cls partial
__device__ int   g_un;                  // unique assigned cells
__device__ int   g_va;                  // valid target count
__device__ int   g_done = 0;            // completion counter

__device__ __forceinline__ float sigf(float z) { return 1.f / (1.f + expf(-z)); }

// anchor match from target data only
__device__ __forceinline__ void anchor_match(float tw, float th, int& bi) {
    float best = -1e30f; bi = 0;
    #pragma unroll
    for (int k = 0; k < 9; k++) {
        float aw = c_anch[2 * k]     * (1.f / 608.f);
        float ah = c_anch[2 * k + 1] * (1.f / 608.f);
        float inter = fminf(tw, aw) * fminf(th, ah);
        float uni   = tw * th + aw * ah - inter;
        float iou   = inter / uni;
        if (iou > best) { best = iou; bi = k; }
    }
}

__global__ void __launch_bounds__(NTHREADS, 1)
fused_kernel(const float* __restrict__ in,
             const float* __restrict__ tgt,
             float* __restrict__ out) {
    __shared__ unsigned bm[NBITWORDS];   // used by dedupe block only
    __shared__ float sm_a[16], sm_b[16];
    __shared__ int   sm_i[16];
    __shared__ int   s_islast;

    int tid = threadIdx.x;
    int w = tid >> 5, l = tid & 31;
    int bid = blockIdx.x;

    // ───────────── phase A ─────────────
    if (bid < CONF_BLOCKS) {
        // conf-plane sigmoid reduction (float4 vectorized)
        int b = bid / AA, a = bid - b * AA;
        const float4* p = (const float4*)(in + (size_t)(b * 255 + a * 85 + 4) * PLANE);
        float s = 0.f;
        for (int i = tid; i < PLANE / 4; i += NTHREADS) {
            float4 v = p[i];
            s += sigf(v.x) + sigf(v.y) + sigf(v.z) + sigf(v.w);
        }
        for (int o = 16; o > 0; o >>= 1) s += __shfl_down_sync(0xffffffffu, s, o);
        if (l == 0) sm_a[w] = s;
        __syncthreads();
        if (tid == 0) {
            float t = 0.f;
            #pragma unroll
            for (int i = 0; i < 16; i++) t += sm_a[i];
            g_confp[bid] = t;
        }
    } else if (bid < DEDUPE_BLOCK) {
        // target blocks: one warp per target, 16 targets/block
        int tb = bid - CONF_BLOCKS;
        int t = tb * 16 + w;

        int b = t / TT;
        const float* t5 = tgt + b * (TT * 5) + (t - b * TT) * 5;
        float tc = t5[0], tx = t5[1], ty = t5[2], tw = t5[3], th = t5[4];
        int valid = ((tc + tx + ty + tw + th) != 0.f);

        int bi; anchor_match(tw, th, bi);
        int assigned = valid && (bi < AA);

        float acc_xy = 0.f, acc_cls = 0.f;
        if (assigned) {
            int a_n = bi;
            int gi = (int)(tx * (float)WW); gi = min(max(gi, 0), WW - 1);
            int gj = (int)(ty * (float)HH); gj = min(max(gj, 0), HH - 1);
            int pos = gj * WW + gi;

            float aw_s = c_anch[2 * a_n], ah_s = c_anch[2 * a_n + 1];
            float tx_t = tx * (float)WW - (float)gi;
            float ty_t = ty * (float)HH - (float)gj;
            float tw_t = logf(tw * 608.f / aw_s);
            float th_t = logf(th * 608.f / ah_s);
            float scale = 2.f * ty * tw;      // faithful to reference quirk
            int ci = (int)tc;

            const float* cp = in + (size_t)(b * 255 + a_n * 85) * PLANE + pos;

            // lanes split the 85 channels (skip conf ch 4)
            #pragma unroll
            for (int r = 0; r < 3; r++) {
                int ch = l + 32 * r;
                if (ch < 85 && ch != 4) {
                    float v = cp[(size_t)ch * PLANE];
                    if (ch == 0)      acc_xy += scale * fabsf(sigf(v) - tx_t);
                    else if (ch == 1) acc_xy += scale * fabsf(sigf(v) - ty_t);
                    else if (ch == 2) acc_xy += scale * fabsf(v - tw_t);
                    else if (ch == 3) acc_xy += scale * fabsf(v - th_t);
                    else {
                        int c = ch - 5;
                        float p = sigf(v);
                        acc_cls += (c == ci) ? -logf(p) : -log1pf(-p);
                    }
                }
            }
        }
        for (int o = 16; o > 0; o >>= 1) {
            acc_xy  += __shfl_down_sync(0xffffffffu, acc_xy, o);
            acc_cls += __shfl_down_sync(0xffffffffu, acc_cls, o);
        }
        if (l == 0) { sm_a[w] = acc_xy; sm_b[w] = acc_cls; }
        __syncthreads();
        if (tid == 0) {
            float sx = 0.f, sc = 0.f;
            #pragma unroll
            for (int i = 0; i < 16; i++) { sx += sm_a[i]; sc += sm_b[i]; }
            g_lxp[tb] = sx;
            g_lcp[tb] = sc;
        }
    } else {
        // dedupe block: everything here depends ONLY on tgt (pure ALU + 16KB reads)
        for (int i = tid; i < NBITWORDS; i += NTHREADS) bm[i] = 0u;
        __syncthreads();

        int va = 0;
        for (int t = tid; t < NT; t += NTHREADS) {
            int b = t / TT;
            const float* t5 = tgt + b * (TT * 5) + (t - b * TT) * 5;
            float tc = t5[0], tx = t5[1], ty = t5[2], tw = t5[3], th = t5[4];
            int valid = ((tc + tx + ty + tw + th) != 0.f);
            va += valid;
            int bi; anchor_match(tw, th, bi);
            if (valid && bi < AA) {
                int gi = (int)(tx * (float)WW); gi = min(max(gi, 0), WW - 1);
                int gj = (int)(ty * (float)HH); gj = min(max(gj, 0), HH - 1);
                int cell = ((b * AA + bi) * HH + gj) * WW + gi;
                atomicOr(&bm[cell >> 5], 1u << (cell & 31));
            }
        }
        __syncthreads();
        // unique = popcount of bitmap (order-free, no first-occurrence scan)
        int un = 0;
        for (int i = tid; i < NBITWORDS; i += NTHREADS) un += __popc(bm[i]);
        for (int o = 16; o > 0; o >>= 1) {
            un += __shfl_down_sync(0xffffffffu, un, o);
            va += __shfl_down_sync(0xffffffffu, va, o);
        }
        if (l == 0) { sm_i[w] = un; sm_a[w] = (float)va; }
        __syncthreads();
        if (tid == 0) {
            int U = 0, V = 0;
            #pragma unroll
            for (int i = 0; i < 16; i++) { U += sm_i[i]; V += (int)sm_a[i]; }
            g_un = U; g_va = V;
        }
    }

    // ───────────── completion protocol (single-thread fence) ─────────────
    __syncthreads();
    if (tid == 0) {
        __threadfence();                      // publish this block's global writes
        int old = atomicAdd(&g_done, 1);
        s_islast = (old == GRID - 1);
    }
    __syncthreads();
    if (!s_islast) return;

    // ───────────── phase B (last block): ~150 scalar loads + tiny sums ─────
    if (tid == 0) __threadfence();            // acquire side
    __syncthreads();

    float cf = 0.f, lx = 0.f, lc = 0.f;
    if (tid < CONF_BLOCKS) cf = g_confp[tid];
    if (tid < TGT_BLOCKS)  { lx = g_lxp[tid]; lc = g_lcp[tid]; }
    for (int o = 16; o > 0; o >>= 1) {
        cf += __shfl_down_sync(0xffffffffu, cf, o);
        lx += __shfl_down_sync(0xffffffffu, lx, o);
        lc += __shfl_down_sync(0xffffffffu, lc, o);
    }
    if (l == 0) { sm_a[w] = cf; sm_b[w] = lx; ((float*)sm_i)[w] = lc; }
    __syncthreads();
    if (tid == 0) {
        float C = 0.f, X = 0.f, L = 0.f;
        #pragma unroll
        for (int i = 0; i < 16; i++) { C += sm_a[i]; X += sm_b[i]; L += ((float*)sm_i)[i]; }
        float nt = fmaxf((float)g_va, 1.f);
        out[0] = C - (float)g_un + X / nt + L;
        g_done = 0;   // reset for next graph replay
    }
}

extern "C" void kernel_launch(void* const* d_in, const int* in_sizes, int n_in,
                              void* d_out, int out_size) {
    const float* in  = (const float*)d_in[0];   // [16, 255, 76, 76]
    const float* tgt = (const float*)d_in[1];   // [16, 250]
    float* out = (float*)d_out;
    fused_kernel<<<GRID, NTHREADS>>>(in, tgt, out);
}

// round 5
// speedup vs baseline: 1.8971x; 1.2390x over previous
#include <cuda_runtime.h>
#include <math.h>

#define BB 16
#define AA 3
#define CC 80
#define HH 76
#define WW 76
#define TT 50
#define PLANE (HH*WW)            // 5776
#define NPLANES (BB*AA)          // 48 conf planes
#define NT (BB*TT)               // 800 targets
#define CONF_BLOCKS NPLANES      // 48
#define TGT_BLOCKS 50            // 16 warps each -> exactly 800 warps
#define DEDUPE_BLOCK (CONF_BLOCKS + TGT_BLOCKS)      // 98
#define GRID (CONF_BLOCKS + TGT_BLOCKS + 1)          // 99 blocks, one wave
#define NTHREADS 512
#define NQ (PLANE/4)                                 // 1444 float4 per plane
#define NBITWORDS ((NPLANES*PLANE + 31)/32)          // 8664 words = 34.7KB

__constant__ float c_anch[18] = {10.f,13.f,16.f,30.f,33.f,23.f,30.f,61.f,62.f,45.f,
                                 59.f,119.f,116.f,90.f,156.f,198.f,373.f,326.f};

__device__ float g_confp[CONF_BLOCKS];  // per-conf-block partial
__device__ float g_lxp[TGT_BLOCKS];     // per-target-block xywh partial
__device__ float g_lcp[TGT_BLOCKS];     // per-target-block cls partial
__device__ int   g_un;                  // unique assigned cells
__device__ int   g_va;                  // valid target count
__device__ int   g_done = 0;            // completion counter

// fast sigmoid: MUFU.EX2 + MUFU.RCP  (rel err ~1e-6, tolerance 1e-3)
__device__ __forceinline__ float sigf(float z) {
    return __fdividef(1.f, 1.f + __expf(-z));
}
// softplus(x) = log(1+exp(x)); BCE on logits, no cancellation:
//   -log(sigmoid(v))   = softplus(-v)
//   -log1p(-sigmoid(v)) = softplus(v)
__device__ __forceinline__ float softplus(float x) {
    return __logf(1.f + __expf(x));
}

// anchor match from target data only
__device__ __forceinline__ void anchor_match(float tw, float th, int& bi) {
    float best = -1e30f; bi = 0;
    #pragma unroll
    for (int k = 0; k < 9; k++) {
        float aw = c_anch[2 * k]     * (1.f / 608.f);
        float ah = c_anch[2 * k + 1] * (1.f / 608.f);
        float inter = fminf(tw, aw) * fminf(th, ah);
        float uni   = tw * th + aw * ah - inter;
        float iou   = __fdividef(inter, uni);
        if (iou > best) { best = iou; bi = k; }
    }
}

__global__ void __launch_bounds__(NTHREADS, 1)
fused_kernel(const float* __restrict__ in,
             const float* __restrict__ tgt,
             float* __restrict__ out) {
    __shared__ unsigned bm[NBITWORDS];   // used by dedupe block only
    __shared__ float sm_a[16], sm_b[16];
    __shared__ int   sm_i[16];
    __shared__ int   s_islast;

    int tid = threadIdx.x;
    int w = tid >> 5, l = tid & 31;
    int bid = blockIdx.x;

    // ───────────── phase A ─────────────
    if (bid < CONF_BLOCKS) {
        // conf-plane sigmoid reduction: 3 explicit loads => MLP=3, one round trip
        int b = bid / AA, a = bid - b * AA;
        const float4* p = (const float4*)(in + (size_t)(b * 255 + a * 85 + 4) * PLANE);
        float4 v0 = p[tid];                 // tid        < 1444 always
        float4 v1 = p[tid + NTHREADS];      // tid+512    < 1444 always (1024+511)
        float4 v2;
        bool has2 = (tid + 2 * NTHREADS) < NQ;   // tid < 420
        if (has2) v2 = p[tid + 2 * NTHREADS];
        float s = sigf(v0.x) + sigf(v0.y) + sigf(v0.z) + sigf(v0.w)
                + sigf(v1.x) + sigf(v1.y) + sigf(v1.z) + sigf(v1.w);
        if (has2) s += sigf(v2.x) + sigf(v2.y) + sigf(v2.z) + sigf(v2.w);

        for (int o = 16; o > 0; o >>= 1) s += __shfl_down_sync(0xffffffffu, s, o);
        if (l == 0) sm_a[w] = s;
        __syncthreads();
        if (tid == 0) {
            float t = 0.f;
            #pragma unroll
            for (int i = 0; i < 16; i++) t += sm_a[i];
            g_confp[bid] = t;
        }
    } else if (bid < DEDUPE_BLOCK) {
        // target blocks: one warp per target, 16 targets/block
        int tb = bid - CONF_BLOCKS;
        int t = tb * 16 + w;

        int b = t / TT;
        const float* t5 = tgt + b * (TT * 5) + (t - b * TT) * 5;
        float tc = t5[0], tx = t5[1], ty = t5[2], tw = t5[3], th = t5[4];
        int valid = ((tc + tx + ty + tw + th) != 0.f);

        int bi; anchor_match(tw, th, bi);
        int assigned = valid && (bi < AA);

        float acc_xy = 0.f, acc_cls = 0.f;
        if (assigned) {
            int a_n = bi;
            int gi = (int)(tx * (float)WW); gi = min(max(gi, 0), WW - 1);
            int gj = (int)(ty * (float)HH); gj = min(max(gj, 0), HH - 1);
            int pos = gj * WW + gi;

            float aw_s = c_anch[2 * a_n], ah_s = c_anch[2 * a_n + 1];
            float tx_t = tx * (float)WW - (float)gi;
            float ty_t = ty * (float)HH - (float)gj;
            float tw_t = __logf(tw * 608.f / aw_s);
            float th_t = __logf(th * 608.f / ah_s);
            float scale = 2.f * ty * tw;      // faithful to reference quirk
            int ci = (int)tc;

            const float* cp = in + (size_t)(b * 255 + a_n * 85) * PLANE + pos;

            // lanes split the 85 channels (skip conf ch 4); issue all loads first
            float v0 = cp[(size_t)l * PLANE];
            float v1 = cp[(size_t)(l + 32) * PLANE];
            float v2 = (l + 64 < 85) ? cp[(size_t)(l + 64) * PLANE] : 0.f;

            // ch = l (0..31)
            if (l == 0)      acc_xy += scale * fabsf(sigf(v0) - tx_t);
            else if (l == 1) acc_xy += scale * fabsf(sigf(v0) - ty_t);
            else if (l == 2) acc_xy += scale * fabsf(v0 - tw_t);
            else if (l == 3) acc_xy += scale * fabsf(v0 - th_t);
            else if (l != 4) acc_cls += softplus((l - 5 == ci) ? -v0 : v0);
            // ch = l+32 (32..63): all cls
            acc_cls += softplus((l + 27 == ci) ? -v1 : v1);
            // ch = l+64 (64..84): cls
            if (l + 64 < 85) acc_cls += softplus((l + 59 == ci) ? -v2 : v2);
        }
        for (int o = 16; o > 0; o >>= 1) {
            acc_xy  += __shfl_down_sync(0xffffffffu, acc_xy, o);
            acc_cls += __shfl_down_sync(0xffffffffu, acc_cls, o);
        }
        if (l == 0) { sm_a[w] = acc_xy; sm_b[w] = acc_cls; }
        __syncthreads();
        if (tid == 0) {
            float sx = 0.f, sc = 0.f;
            #pragma unroll
            for (int i = 0; i < 16; i++) { sx += sm_a[i]; sc += sm_b[i]; }
            g_lxp[tb] = sx;
            g_lcp[tb] = sc;
        }
    } else {
        // dedupe block: depends ONLY on tgt (pure ALU + 16KB reads)
        for (int i = tid; i < NBITWORDS; i += NTHREADS) bm[i] = 0u;
        __syncthreads();

        int va = 0;
        for (int t = tid; t < NT; t += NTHREADS) {
            int b = t / TT;
            const float* t5 = tgt + b * (TT * 5) + (t - b * TT) * 5;
            float tc = t5[0], tx = t5[1], ty = t5[2], tw = t5[3], th = t5[4];
            int valid = ((tc + tx + ty + tw + th) != 0.f);
            va += valid;
            int bi; anchor_match(tw, th, bi);
            if (valid && bi < AA) {
                int gi = (int)(tx * (float)WW); gi = min(max(gi, 0), WW - 1);
                int gj = (int)(ty * (float)HH); gj = min(max(gj, 0), HH - 1);
                int cell = ((b * AA + bi) * HH + gj) * WW + gi;
                atomicOr(&bm[cell >> 5], 1u << (cell & 31));
            }
        }
        __syncthreads();
        int un = 0;
        for (int i = tid; i < NBITWORDS; i += NTHREADS) un += __popc(bm[i]);
        for (int o = 16; o > 0; o >>= 1) {
            un += __shfl_down_sync(0xffffffffu, un, o);
            va += __shfl_down_sync(0xffffffffu, va, o);
        }
        if (l == 0) { sm_i[w] = un; sm_a[w] = (float)va; }
        __syncthreads();
        if (tid == 0) {
            int U = 0, V = 0;
            #pragma unroll
            for (int i = 0; i < 16; i++) { U += sm_i[i]; V += (int)sm_a[i]; }
            g_un = U; g_va = V;
        }
    }

    // ───────────── completion protocol ─────────────
    // only tid 0 wrote globals, and its writes are program-ordered before the
    // fence, so no extra __syncthreads is needed before it.
    if (tid == 0) {
        __threadfence();                      // publish this block's global writes
        int old = atomicAdd(&g_done, 1);
        s_islast = (old == GRID - 1);
    }
    __syncthreads();
    if (!s_islast) return;

    // ───────────── phase B (last block): ~150 scalar loads + tiny sums ─────
    if (tid == 0) __threadfence();            // acquire side
    __syncthreads();

    float cf = 0.f, lx = 0.f, lc = 0.f;
    if (tid < CONF_BLOCKS) cf = g_confp[tid];
    if (tid < TGT_BLOCKS)  { lx = g_lxp[tid]; lc = g_lcp[tid]; }
    for (int o = 16; o > 0; o >>= 1) {
        cf += __shfl_down_sync(0xffffffffu, cf, o);
        lx += __shfl_down_sync(0xffffffffu, lx, o);
        lc += __shfl_down_sync(0xffffffffu, lc, o);
    }
    if (l == 0) { sm_a[w] = cf; sm_b[w] = lx; ((float*)sm_i)[w] = lc; }
    __syncthreads();
    if (tid == 0) {
        float C = 0.f, X = 0.f, L = 0.f;
        #pragma unroll
        for (int i = 0; i < 16; i++) { C += sm_a[i]; X += sm_b[i]; L += ((float*)sm_i)[i]; }
        float nt = fmaxf((float)g_va, 1.f);
        out[0] = C - (float)g_un + X / nt + L;
        g_done = 0;   // reset for next graph replay
    }
}

extern "C" void kernel_launch(void* const* d_in, const int* in_sizes, int n_in,
                              void* d_out, int out_size) {
    const float* in  = (const float*)d_in[0];   // [16, 255, 76, 76]
    const float* tgt = (const float*)d_in[1];   // [16, 250]
    float* out = (float*)d_out;
    fused_kernel<<<GRID, NTHREADS>>>(in, tgt, out);
}